// round 11
// baseline (speedup 1.0000x reference)
#include <cuda_runtime.h>
#include <float.h>
#include <stdint.h>

// Fixed problem shape
#define KC      512         // codebook size
#define DC      64          // code dim
#define HWC     4096        // H*W
#define NC      131072      // B*H*W
#define TPB     256
#define PPT     2           // pixels per thread
#define TILE    (TPB*PPT)   // 512 pixels per tile
#define NTILES  (NC/TILE)   // 256 tiles
#define GRIDP   128         // 2 tiles per CTA, perfectly balanced
#define KB      8           // codes per k-block -> 4 u64 accums per pixel
#define ETS     520         // padded row stride (floats), rows 16B-aligned

// smem floats: ET[64][520] + enorm[512] + red[256]
#define ET_FLOATS   (DC * ETS)
#define SMEM_FLOATS (ET_FLOATS + KC + TPB)
#define SMEM_BYTES  (SMEM_FLOATS * 4)

__device__ float    g_part[NTILES];
__device__ unsigned g_done;         // zero-init; finalizer resets each launch

typedef unsigned long long u64;

__device__ __forceinline__ u64 pack2(float x, float y) {
    u64 r;
    asm("mov.b64 %0, {%1, %2};" : "=l"(r) : "f"(x), "f"(y));
    return r;
}
__device__ __forceinline__ void unpack2(u64 v, float& x, float& y) {
    asm("mov.b64 {%0, %1}, %2;" : "=f"(x), "=f"(y) : "l"(v));
}
__device__ __forceinline__ float lo2(u64 v) {
    float x, y;
    asm("mov.b64 {%0, %1}, %2;" : "=f"(x), "=f"(y) : "l"(v));
    return x;
}
__device__ __forceinline__ u64 ffma2(u64 a, u64 b, u64 c) {
    u64 d;
    asm("fma.rn.f32x2 %0, %1, %2, %3;" : "=l"(d) : "l"(a), "l"(b), "l"(c));
    return d;
}

__global__ __launch_bounds__(TPB, 1)
void vq_kernel(const float* __restrict__ latents,
               const float* __restrict__ embedding,
               float* __restrict__ out,
               float* __restrict__ loss_out) {
    extern __shared__ float smem[];
    float* ET    = smem;                 // [64][520], ET[d*ETS + k]
    float* eNorm = smem + ET_FLOATS;     // [512]
    float* red   = eNorm + KC;           // [256]

    const int tid = threadIdx.x;

    // ---- stage transposed codebook once per CTA ----
    {
        const float4* src = reinterpret_cast<const float4*>(embedding);
        #pragma unroll
        for (int i4 = tid; i4 < (KC * DC) / 4; i4 += TPB) {
            float4 v = src[i4];
            int i = i4 * 4;
            int k = i >> 6;
            int d = i & 63;
            ET[(d + 0) * ETS + k] = v.x;
            ET[(d + 1) * ETS + k] = v.y;
            ET[(d + 2) * ETS + k] = v.z;
            ET[(d + 3) * ETS + k] = v.w;
        }
    }
    __syncthreads();

    // ---- enorm_k: sequential d, separate mul/add (XLA reduce emulation) ----
    #pragma unroll
    for (int k = tid; k < KC; k += TPB) {
        float s = 0.0f;
        #pragma unroll
        for (int d = 0; d < DC; ++d) {
            float e = ET[d * ETS + k];
            s = __fadd_rn(s, __fmul_rn(e, e));
        }
        eNorm[k] = s;
    }
    __syncthreads();

    // ---- persistent tile loop: 2 tiles of 512 pixels per CTA ----
    for (int tile = blockIdx.x; tile < NTILES; tile += GRIDP) {
        const int pA = tile * TILE + tid;        // pixel A
        const int pB = pA + TPB;                 // pixel B
        const int bA = pA >> 12, hwA = pA & (HWC - 1);
        const int bB = pB >> 12, hwB = pB & (HWC - 1);
        const float* latA = latents + (size_t)bA * DC * HWC + hwA;
        const float* latB = latents + (size_t)bB * DC * HWC + hwB;

        // latent vectors, pre-packed as {f,f} u64 (no per-iteration MOVs)
        u64   f2A[DC], f2B[DC];
        float fnA = 0.0f, fnB = 0.0f;
        #pragma unroll
        for (int d = 0; d < DC; ++d) {
            float a = latA[d * HWC];
            float b = latB[d * HWC];
            f2A[d] = pack2(a, a);
            f2B[d] = pack2(b, b);
            fnA = __fadd_rn(fnA, __fmul_rn(a, a));
            fnB = __fadd_rn(fnB, __fmul_rn(b, b));
        }

        float bestA = FLT_MAX, bestB = FLT_MAX;
        int   bkA = 0, bkB = 0;

        // ---- argmin over K: 8 codes per k-block, depth-2 rotated e-loads ----
        #pragma unroll 1
        for (int k0 = 0; k0 < KC; k0 += KB) {
            u64 aA0 = 0, aA1 = 0, aA2 = 0, aA3 = 0;
            u64 aB0 = 0, aB1 = 0, aB2 = 0, aB3 = 0;

            // prime pipeline with d=0 and d=1 codes
            const ulonglong2* r0 =
                reinterpret_cast<const ulonglong2*>(ET + 0 * ETS + k0);
            const ulonglong2* r1 =
                reinterpret_cast<const ulonglong2*>(ET + 1 * ETS + k0);
            ulonglong2 c0 = r0[0], c1 = r0[1];   // current (d)
            ulonglong2 n0 = r1[0], n1 = r1[1];   // next (d+1)

            #pragma unroll
            for (int d = 0; d < DC; ++d) {
                ulonglong2 t0 = c0, t1 = c1;     // init avoids uninit warnings
                if (d + 2 < DC) {                // compile-time under full unroll
                    const ulonglong2* r2 =
                        reinterpret_cast<const ulonglong2*>(ET + (d + 2) * ETS + k0);
                    t0 = r2[0];
                    t1 = r2[1];
                }
                const u64 mA = f2A[d];
                const u64 mB = f2B[d];
                aA0 = ffma2(mA, c0.x, aA0);   aB0 = ffma2(mB, c0.x, aB0);
                aA1 = ffma2(mA, c0.y, aA1);   aB1 = ffma2(mB, c0.y, aB1);
                aA2 = ffma2(mA, c1.x, aA2);   aB2 = ffma2(mB, c1.x, aB2);
                aA3 = ffma2(mA, c1.y, aA3);   aB3 = ffma2(mB, c1.y, aB3);
                c0 = n0; c1 = n1;
                n0 = t0; n1 = t1;
            }

            // score (ascending k => first-min preserved)
            u64 accA[4] = {aA0, aA1, aA2, aA3};
            u64 accB[4] = {aB0, aB1, aB2, aB3};
            #pragma unroll
            for (int j = 0; j < 4; ++j) {
                int k = k0 + 2 * j;
                float en0 = eNorm[k];
                float en1 = eNorm[k + 1];
                float aAx, aAy, aBx, aBy;
                unpack2(accA[j], aAx, aAy);
                unpack2(accB[j], aBx, aBy);
                float sA0 = __fsub_rn(__fadd_rn(fnA, en0), __fmul_rn(2.0f, aAx));
                float sA1 = __fsub_rn(__fadd_rn(fnA, en1), __fmul_rn(2.0f, aAy));
                float sB0 = __fsub_rn(__fadd_rn(fnB, en0), __fmul_rn(2.0f, aBx));
                float sB1 = __fsub_rn(__fadd_rn(fnB, en1), __fmul_rn(2.0f, aBy));
                bkA = (sA0 < bestA) ? k     : bkA;  bestA = fminf(sA0, bestA);
                bkA = (sA1 < bestA) ? k + 1 : bkA;  bestA = fminf(sA1, bestA);
                bkB = (sB0 < bestB) ? k     : bkB;  bestB = fminf(sB0, bestB);
                bkB = (sB1 < bestB) ? k + 1 : bkB;  bestB = fminf(sB1, bestB);
            }
        }

        // ---- epilogue: gather codes, STE outputs, per-pixel loss partials ----
        float* outA = out + (size_t)bA * DC * HWC + hwA;
        float* outB = out + (size_t)bB * DC * HWC + hwB;
        float ldist = 0.0f;
        #pragma unroll
        for (int d = 0; d < DC; ++d) {
            float qA = ET[d * ETS + bkA];
            float qB = ET[d * ETS + bkB];
            float fa = lo2(f2A[d]);
            float fb = lo2(f2B[d]);
            float dqA = __fsub_rn(qA, fa);
            float dqB = __fsub_rn(qB, fb);
            ldist = __fadd_rn(ldist, __fmul_rn(dqA, dqA));
            ldist = __fadd_rn(ldist, __fmul_rn(dqB, dqB));
            outA[d * HWC] = __fadd_rn(fa, dqA);
            outB[d * HWC] = __fadd_rn(fb, dqB);
        }

        // ---- per-tile deterministic tree reduce -> g_part[tile] ----
        red[tid] = ldist;
        __syncthreads();
        #pragma unroll
        for (int s = TPB / 2; s > 0; s >>= 1) {
            if (tid < s) red[tid] += red[tid + s];
            __syncthreads();
        }
        if (tid == 0) g_part[tile] = red[0];
        __syncthreads();   // red[] reused next tile
    }

    // ---- grid finalize: last CTA reduces the 256 tile partials ----
    __shared__ unsigned s_last;
    __threadfence();
    if (tid == 0) s_last = (atomicAdd(&g_done, 1u) == GRIDP - 1u);
    __syncthreads();

    if (s_last) {
        red[tid] = g_part[tid];
        __syncthreads();
        #pragma unroll
        for (int s = TPB / 2; s > 0; s >>= 1) {
            if (tid < s) red[tid] += red[tid + s];
            __syncthreads();
        }
        if (tid == 0) {
            float m = red[0] / 8388608.0f;                   // exact /2^23
            *loss_out = __fadd_rn(__fmul_rn(m, 0.25f), m);   // fl(0.25m)+m
            g_done = 0;                                      // reset for replay
        }
    }
}

extern "C" void kernel_launch(void* const* d_in, const int* in_sizes, int n_in,
                              void* d_out, int out_size) {
    const float* latents   = (const float*)d_in[0];   // [32,64,64,64] fp32
    const float* embedding = (const float*)d_in[1];   // [512,64] fp32
    float* out  = (float*)d_out;                      // tensor, then loss scalar
    float* loss = out + (out_size - 1);

    cudaFuncSetAttribute(vq_kernel, cudaFuncAttributeMaxDynamicSharedMemorySize, SMEM_BYTES);
    vq_kernel<<<GRIDP, TPB, SMEM_BYTES>>>(latents, embedding, out, loss);
}